// round 5
// baseline (speedup 1.0000x reference)
#include <cuda_runtime.h>
#include <cstdint>

#define NN   25000
#define NE   100000
#define HD   32
#define NCL  8000
#define NA   50000
#define NEC  24000
#define EDIM 8

typedef unsigned long long u64;

// ---------------- scratch (device globals; zero-initialized at load) -----------
__device__ float g_x[NN * HD];
__device__ float g_c[NCL * HD];
__device__ float g_h[(2 * NE + 2 * NEC) * HD];   // all 4 edge-MLP outputs
__device__ float g_P[(size_t)NN * HD * HD];      // 102.4 MB
__device__ float g_Q[NN * HD];
__device__ float g_aggn[NN * HD];                // kept zero between calls
__device__ float g_aggc[NCL * HD];               // kept zero between calls
__device__ float g_m[NN * HD];
__device__ int   g_deg[2 * NN + 2 * NCL];        // [dst | cdst | cid | nid]

// ---------------- f32x2 packed helpers ------------------------------------------
__device__ __forceinline__ u64 pk2(float v) {
    u64 r; asm("mov.b64 %0,{%1,%1};" : "=l"(r) : "f"(v)); return r;
}
__device__ __forceinline__ u64 fma2(u64 a, u64 b, u64 c) {
    u64 d; asm("fma.rn.f32x2 %0,%1,%2,%3;" : "=l"(d) : "l"(a), "l"(b), "l"(c)); return d;
}

// ---------------- setup ----------------------------------------------------------
__global__ void k_zero_deg(int* __restrict__ p, int n) {
    int i = blockIdx.x * blockDim.x + threadIdx.x;
    if (i < n) p[i] = 0;
}

__global__ void k_count_all(const int* __restrict__ dst, const int* __restrict__ cdst,
                            const int* __restrict__ nid, const int* __restrict__ cid,
                            int* __restrict__ deg) {
    int i = blockIdx.x * blockDim.x + threadIdx.x;
    if (i < NE) {
        atomicAdd(&deg[dst[i]], 1);
    } else if (i < NE + NEC) {
        atomicAdd(&deg[NN + cdst[i - NE]], 1);
    } else if (i < NE + NEC + NA) {
        int j = i - NE - NEC;
        atomicAdd(&deg[NN + NCL + cid[j]], 1);
        atomicAdd(&deg[NN + 2 * NCL + nid[j]], 1);
    }
}

// ---------------- ALL edge MLPs (both graphs x both layers), warp per edge-row ----
// h layout: [l0 node NE | l1 node NE | l0 cliq NEC | l1 cliq NEC] x HD
__global__ void k_edge_mlp_all(const float* __restrict__ ef_n, const float* __restrict__ ef_c,
                               const float* __restrict__ nn1_w, const float* __restrict__ nn1_b,
                               const float* __restrict__ cnn1_w, const float* __restrict__ cnn1_b,
                               float* __restrict__ h) {
    int w = (blockIdx.x * blockDim.x + threadIdx.x) >> 5;
    int lane = threadIdx.x & 31;
    const float* ef; const float* w1; const float* b1; float* ho;
    if (w < 2 * NE) {
        int layer = w / NE, e = w - layer * NE;
        ef = ef_n + (size_t)e * EDIM;
        w1 = nn1_w + layer * EDIM * HD;
        b1 = nn1_b + layer * HD;
        ho = h + (size_t)(layer * NE + e) * HD;
    } else if (w < 2 * NE + 2 * NEC) {
        int w2 = w - 2 * NE;
        int layer = w2 / NEC, e = w2 - layer * NEC;
        ef = ef_c + (size_t)e * EDIM;
        w1 = cnn1_w + layer * EDIM * HD;
        b1 = cnn1_b + layer * HD;
        ho = h + (size_t)(2 * NE + layer * NEC + e) * HD;
    } else return;

    float ev = (lane < EDIM) ? ef[lane] : 0.f;
    float acc = b1[lane];
#pragma unroll
    for (int j = 0; j < EDIM; j++)
        acc += __shfl_sync(0xffffffffu, ev, j) * w1[j * HD + lane];
    ho[lane] = fmaxf(acc, 0.f);
}

// ---------------- P = X @ T (FFMA2) + Q slice -------------------------------------
// blockIdx.y < 8 : 128x128 P tile; blockIdx.y == 8 : Q rows (warp per row).
// T[i, k*32+o] = w2[k*1024 + i*32 + o]; permutation folded into B-tile load.
__global__ __launch_bounds__(256, 2)
void k_gemmPQ(const float* __restrict__ X, int nrows,
              const float* __restrict__ w2, const float* __restrict__ b2,
              float* __restrict__ P, float* __restrict__ Q) {
    int tid  = threadIdx.x;
    int row0 = blockIdx.x * 128;

    if (blockIdx.y == 8) {
        // Q[r,o] = sum_i X[r,i] * b2[i*32+o]
        int wp = tid >> 5, lane = tid & 31;
        for (int it = 0; it < 16; it++) {
            int r = row0 + it * 8 + wp;
            if (r >= nrows) return;
            float xv = X[(size_t)r * HD + lane];
            float acc = 0.f;
#pragma unroll
            for (int i = 0; i < HD; i++)
                acc += __shfl_sync(0xffffffffu, xv, i) * b2[i * HD + lane];
            Q[(size_t)r * HD + lane] = acc;
        }
        return;
    }

    __shared__ float As[HD][128];
    __shared__ float Bs[HD][128];
    int col0 = blockIdx.y * 128;

    {
        int r = tid >> 3;
        int q = tid & 7;
        for (int rr = r; rr < 128; rr += 32) {
            int row = row0 + rr;
            float4 v = make_float4(0.f, 0.f, 0.f, 0.f);
            if (row < nrows) v = *(const float4*)(X + (size_t)row * HD + q * 4);
            As[q * 4 + 0][rr] = v.x;
            As[q * 4 + 1][rr] = v.y;
            As[q * 4 + 2][rr] = v.z;
            As[q * 4 + 3][rr] = v.w;
        }
    }
    {
        int r = tid >> 5;
        int q = tid & 31;
        int C = col0 + q * 4;
        int kcol = C >> 5, o = C & 31;
        for (int kk = r; kk < HD; kk += 8) {
            float4 v = *(const float4*)(w2 + kcol * (HD * HD) + kk * HD + o);
            *(float4*)&Bs[kk][q * 4] = v;
        }
    }
    __syncthreads();

    int tr = (tid >> 4) * 8;
    int tc = (tid & 15) * 8;
    u64 acc[8][4];
#pragma unroll
    for (int a = 0; a < 8; a++)
#pragma unroll
        for (int b = 0; b < 4; b++) acc[a][b] = 0ULL;

#pragma unroll
    for (int k = 0; k < HD; k++) {
        float a[8];
        *(float4*)&a[0] = *(float4*)&As[k][tr];
        *(float4*)&a[4] = *(float4*)&As[k][tr + 4];
        u64 bp[4];
        bp[0] = *(const u64*)&Bs[k][tc];
        bp[1] = *(const u64*)&Bs[k][tc + 2];
        bp[2] = *(const u64*)&Bs[k][tc + 4];
        bp[3] = *(const u64*)&Bs[k][tc + 6];
#pragma unroll
        for (int i = 0; i < 8; i++) {
            u64 ad = pk2(a[i]);
#pragma unroll
            for (int j = 0; j < 4; j++)
                acc[i][j] = fma2(ad, bp[j], acc[i][j]);
        }
    }

#pragma unroll
    for (int i = 0; i < 8; i++) {
        int row = row0 + tr + i;
        if (row < nrows) {
            u64* dstp = (u64*)(P + (size_t)row * (HD * HD) + col0 + tc);
#pragma unroll
            for (int j = 0; j < 4; j++) dstp[j] = acc[i][j];
        }
    }
}

// ---------------- per-edge message + scatter-add (unchanged from R4) --------------
__global__ void k_edge_msg(int nE, const int* __restrict__ src, const int* __restrict__ dst,
                           const float* __restrict__ h, const float* __restrict__ P,
                           const float* __restrict__ Q, float* __restrict__ agg) {
    int e = (blockIdx.x * blockDim.x + threadIdx.x) >> 5;
    int lane = threadIdx.x & 31;
    if (e >= nE) return;
    int s = src[e];
    int d = dst[e];
    float hv = h[(size_t)e * HD + lane];
    const float4* Pr = (const float4*)(P + (size_t)s * (HD * HD));
    int kq = lane >> 3;
    int og = lane & 7;

    float a0 = 0.f, a1 = 0.f, a2 = 0.f, a3 = 0.f;
#pragma unroll
    for (int it = 0; it < 8; it++) {
        int k = it * 4 + kq;
        float hk = __shfl_sync(0xffffffffu, hv, k);
        float4 v = Pr[k * 8 + og];
        a0 += hk * v.x; a1 += hk * v.y; a2 += hk * v.z; a3 += hk * v.w;
    }
#pragma unroll
    for (int m = 8; m <= 16; m <<= 1) {
        a0 += __shfl_xor_sync(0xffffffffu, a0, m);
        a1 += __shfl_xor_sync(0xffffffffu, a1, m);
        a2 += __shfl_xor_sync(0xffffffffu, a2, m);
        a3 += __shfl_xor_sync(0xffffffffu, a3, m);
    }
    if (lane < 8) {
        float4 q = *(const float4*)(Q + (size_t)s * HD + lane * 4);
        float* ag = agg + (size_t)d * HD + lane * 4;
        atomicAdd(ag + 0, a0 + q.x);
        atomicAdd(ag + 1, a1 + q.y);
        atomicAdd(ag + 2, a2 + q.z);
        atomicAdd(ag + 3, a3 + q.w);
    }
}

// ---------------- finalize + project; re-zeros agg after consuming ---------------
__global__ void k_finalize_proj(const float* __restrict__ Xin, float* __restrict__ Xout,
                                float* __restrict__ agg, const int* __restrict__ deg,
                                const float* __restrict__ rw, const float* __restrict__ rb,
                                const float* __restrict__ pw, const float* __restrict__ pb,
                                float* __restrict__ m, int nrows,
                                float* __restrict__ copy_out) {
    __shared__ float Rs[HD][HD], Pw[HD][HD];
    for (int i = threadIdx.x; i < HD * HD; i += blockDim.x) {
        Rs[i >> 5][i & 31] = rw[i];
        Pw[i >> 5][i & 31] = pw[i];
    }
    __syncthreads();

    int r = (blockIdx.x * blockDim.x + threadIdx.x) >> 5;
    int lane = threadIdx.x & 31;
    if (r >= nrows) return;
    float xv = Xin[(size_t)r * HD + lane];
    float av = agg[(size_t)r * HD + lane];
    agg[(size_t)r * HD + lane] = 0.f;            // restore zero invariant
    float acc = rb[lane] + av / fmaxf((float)deg[r], 1.f);
#pragma unroll
    for (int i = 0; i < HD; i++)
        acc += __shfl_sync(0xffffffffu, xv, i) * Rs[i][lane];
    float xn = fmaxf(acc, 0.f);
    Xout[(size_t)r * HD + lane] = xn;
    if (copy_out) copy_out[(size_t)r * HD + lane] = xn;
    float macc = pb[lane];
#pragma unroll
    for (int i = 0; i < HD; i++)
        macc += __shfl_sync(0xffffffffu, xn, i) * Pw[i][lane];
    m[(size_t)r * HD + lane] = macc;
}

// ---------------- scatter + mean residual (addmean re-zeros agg) ------------------
__global__ void k_scatter(int nA, const int* __restrict__ from, const int* __restrict__ to,
                          const float* __restrict__ m, float* __restrict__ agg) {
    int a = (blockIdx.x * blockDim.x + threadIdx.x) >> 5;
    int lane = threadIdx.x & 31;
    if (a >= nA) return;
    float v = m[(size_t)from[a] * HD + lane];
    atomicAdd(&agg[(size_t)to[a] * HD + lane], v);
}

__global__ void k_addmean(const float* __restrict__ in, float* __restrict__ out,
                          float* __restrict__ agg, const int* __restrict__ deg,
                          int nrows) {
    int i = blockIdx.x * blockDim.x + threadIdx.x;
    if (i >= nrows * HD) return;
    float av = agg[i];
    agg[i] = 0.f;                                // restore zero invariant
    out[i] = in[i] + av / fmaxf((float)deg[i >> 5], 1.f);
}

// ===================================================================================
static inline int cdiv(int a, int b) { return (a + b - 1) / b; }

extern "C" void kernel_launch(void* const* d_in, const int* in_sizes, int n_in,
                              void* d_out, int out_size) {
    const float* node_features   = (const float*)d_in[0];
    const int*   edge_index      = (const int*)d_in[1];
    const float* edge_features   = (const float*)d_in[2];
    const float* clique_features = (const float*)d_in[3];
    const int*   n2c_index       = (const int*)d_in[4];
    const int*   cedge_index     = (const int*)d_in[5];
    const float* cedge_features  = (const float*)d_in[6];
    const float* nn1_w  = (const float*)d_in[7];
    const float* nn1_b  = (const float*)d_in[8];
    const float* nn2_w  = (const float*)d_in[9];
    const float* nn2_b  = (const float*)d_in[10];
    const float* root_w = (const float*)d_in[11];
    const float* root_b = (const float*)d_in[12];
    const float* n2c_w  = (const float*)d_in[13];
    const float* n2c_b  = (const float*)d_in[14];
    const float* cnn1_w = (const float*)d_in[15];
    const float* cnn1_b = (const float*)d_in[16];
    const float* cnn2_w = (const float*)d_in[17];
    const float* cnn2_b = (const float*)d_in[18];
    const float* croot_w = (const float*)d_in[19];
    const float* croot_b = (const float*)d_in[20];
    const float* c2n_w  = (const float*)d_in[21];
    const float* c2n_b  = (const float*)d_in[22];
    float* out = (float*)d_out;

    const int* src  = edge_index;
    const int* dst  = edge_index + NE;
    const int* nid  = n2c_index;
    const int* cid  = n2c_index + NA;
    const int* csrc = cedge_index;
    const int* cdst = cedge_index + NEC;

    float *x, *c, *h, *P, *Q, *aggn, *aggc, *m;
    int* deg;
    cudaGetSymbolAddress((void**)&x, g_x);
    cudaGetSymbolAddress((void**)&c, g_c);
    cudaGetSymbolAddress((void**)&h, g_h);
    cudaGetSymbolAddress((void**)&P, g_P);
    cudaGetSymbolAddress((void**)&Q, g_Q);
    cudaGetSymbolAddress((void**)&aggn, g_aggn);
    cudaGetSymbolAddress((void**)&aggc, g_aggc);
    cudaGetSymbolAddress((void**)&m, g_m);
    cudaGetSymbolAddress((void**)&deg, g_deg);
    const int* deg_dst  = deg;
    const int* deg_cdst = deg + NN;
    const int* deg_cid  = deg + NN + NCL;
    const int* deg_nid  = deg + NN + 2 * NCL;

    const int TB = 256;
    const int DEG_N = 2 * NN + 2 * NCL;
    dim3 gemmGridN(cdiv(NN, 128), 9);   // y==8 is the Q slice
    dim3 gemmGridC(cdiv(NCL, 128), 9);

    // ---- setup: launches #1-3 ----
    k_zero_deg<<<cdiv(DEG_N, TB), TB>>>(deg, DEG_N);
    k_count_all<<<cdiv(NE + NEC + NA, TB), TB>>>(dst, cdst, nid, cid, deg);
    k_edge_mlp_all<<<cdiv((2 * NE + 2 * NEC) * 32, TB), TB>>>(
        edge_features, cedge_features, nn1_w, nn1_b, cnn1_w, cnn1_b, h);

    for (int l = 0; l < 2; l++) {
        const float* xin = (l == 0) ? node_features : x;
        const float* cin = (l == 0) ? clique_features : c;
        int po = l * HD * HD, bo = l * HD;
        const float* h_n = h + (size_t)l * NE * HD;
        const float* h_c = h + (size_t)(2 * NE + l * NEC) * HD;

        // ---- node NNConv ----  (launch #4 on l=0: gemmPQ, profiled)
        k_gemmPQ<<<gemmGridN, 256>>>(xin, NN, nn2_w + l * HD * HD * HD, nn2_b + po, P, Q);
        k_edge_msg<<<cdiv(NE * 32, TB), TB>>>(NE, src, dst, h_n, P, Q, aggn);
        k_finalize_proj<<<cdiv(NN * 32, TB), TB>>>(xin, x, aggn, deg_dst,
                                                   root_w + po, root_b + bo,
                                                   n2c_w + po, n2c_b + bo,
                                                   m, NN, nullptr);
        // ---- Node2Clique ----
        k_scatter<<<cdiv(NA * 32, TB), TB>>>(NA, nid, cid, m, aggc);
        k_addmean<<<cdiv(NCL * HD, TB), TB>>>(cin, c, aggc, deg_cid, NCL);

        // ---- clique NNConv ----
        k_gemmPQ<<<gemmGridC, 256>>>(c, NCL, cnn2_w + l * HD * HD * HD, cnn2_b + po, P, Q);
        k_edge_msg<<<cdiv(NEC * 32, TB), TB>>>(NEC, csrc, cdst, h_c, P, Q, aggc);
        k_finalize_proj<<<cdiv(NCL * 32, TB), TB>>>(c, c, aggc, deg_cdst,
                                                    croot_w + po, croot_b + bo,
                                                    c2n_w + po, c2n_b + bo,
                                                    m, NCL,
                                                    (l == 1) ? (out + (size_t)NN * HD) : nullptr);
        // ---- Clique2Node ----
        k_scatter<<<cdiv(NA * 32, TB), TB>>>(NA, cid, nid, m, aggn);
        k_addmean<<<cdiv(NN * HD, TB), TB>>>(x, (l == 1) ? out : x, aggn, deg_nid, NN);
    }
}

// round 6
// speedup vs baseline: 1.1097x; 1.1097x over previous
#include <cuda_runtime.h>
#include <cstdint>

#define NN   25000
#define NE   100000
#define HD   32
#define NCL  8000
#define NA   50000
#define NEC  24000
#define EDIM 8

// ---------------- scratch (device globals; zero-initialized at load) -----------
__device__ float g_x[NN * HD];
__device__ float g_c[NCL * HD];
__device__ float g_h[(2 * NE + 2 * NEC) * HD];   // all 4 edge-MLP outputs
__device__ float g_P[(size_t)NN * HD * HD];      // 102.4 MB
__device__ float g_Q[NN * HD];
__device__ float g_aggn[NN * HD];                // kept zero between calls
__device__ float g_aggc[NCL * HD];               // kept zero between calls
__device__ float g_m[NN * HD];
__device__ int   g_deg[2 * NN + 2 * NCL];        // [dst | cdst | cid | nid]

// ---------------- setup ----------------------------------------------------------
__global__ void k_zero_deg(int* __restrict__ p, int n) {
    int i = blockIdx.x * blockDim.x + threadIdx.x;
    if (i < n) p[i] = 0;
}

__global__ void k_count_all(const int* __restrict__ dst, const int* __restrict__ cdst,
                            const int* __restrict__ nid, const int* __restrict__ cid,
                            int* __restrict__ deg) {
    int i = blockIdx.x * blockDim.x + threadIdx.x;
    if (i < NE) {
        atomicAdd(&deg[dst[i]], 1);
    } else if (i < NE + NEC) {
        atomicAdd(&deg[NN + cdst[i - NE]], 1);
    } else if (i < NE + NEC + NA) {
        int j = i - NE - NEC;
        atomicAdd(&deg[NN + NCL + cid[j]], 1);
        atomicAdd(&deg[NN + 2 * NCL + nid[j]], 1);
    }
}

// ---------------- ALL edge MLPs (both graphs x both layers), warp per edge-row ----
// h layout: [l0 node NE | l1 node NE | l0 cliq NEC | l1 cliq NEC] x HD
__global__ void k_edge_mlp_all(const float* __restrict__ ef_n, const float* __restrict__ ef_c,
                               const float* __restrict__ nn1_w, const float* __restrict__ nn1_b,
                               const float* __restrict__ cnn1_w, const float* __restrict__ cnn1_b,
                               float* __restrict__ h) {
    int w = (blockIdx.x * blockDim.x + threadIdx.x) >> 5;
    int lane = threadIdx.x & 31;
    const float* ef; const float* w1; const float* b1; float* ho;
    if (w < 2 * NE) {
        int layer = w / NE, e = w - layer * NE;
        ef = ef_n + (size_t)e * EDIM;
        w1 = nn1_w + layer * EDIM * HD;
        b1 = nn1_b + layer * HD;
        ho = h + (size_t)(layer * NE + e) * HD;
    } else if (w < 2 * NE + 2 * NEC) {
        int w2 = w - 2 * NE;
        int layer = w2 / NEC, e = w2 - layer * NEC;
        ef = ef_c + (size_t)e * EDIM;
        w1 = cnn1_w + layer * EDIM * HD;
        b1 = cnn1_b + layer * HD;
        ho = h + (size_t)(2 * NE + layer * NEC + e) * HD;
    } else return;

    float ev = (lane < EDIM) ? ef[lane] : 0.f;
    float acc = b1[lane];
#pragma unroll
    for (int j = 0; j < EDIM; j++)
        acc += __shfl_sync(0xffffffffu, ev, j) * w1[j * HD + lane];
    ho[lane] = fmaxf(acc, 0.f);
}

// ---------------- P = X @ T (scalar FFMA, R4-proven body) + Q slice ----------------
// blockIdx.y < 8 : 128x128 P tile; blockIdx.y == 8 : Q rows (warp per row).
// T[i, k*32+o] = w2[k*1024 + i*32 + o]; permutation folded into B-tile load.
__global__ __launch_bounds__(256, 2)
void k_gemmPQ(const float* __restrict__ X, int nrows,
              const float* __restrict__ w2, const float* __restrict__ b2,
              float* __restrict__ P, float* __restrict__ Q) {
    int tid  = threadIdx.x;
    int row0 = blockIdx.x * 128;

    if (blockIdx.y == 8) {
        // Q[r,o] = sum_i X[r,i] * b2[i*32+o]
        int wp = tid >> 5, lane = tid & 31;
        for (int it = 0; it < 16; it++) {
            int r = row0 + it * 8 + wp;
            if (r >= nrows) return;
            float xv = X[(size_t)r * HD + lane];
            float acc = 0.f;
#pragma unroll
            for (int i = 0; i < HD; i++)
                acc += __shfl_sync(0xffffffffu, xv, i) * b2[i * HD + lane];
            Q[(size_t)r * HD + lane] = acc;
        }
        return;
    }

    __shared__ float As[HD][128];
    __shared__ float Bs[HD][128];
    int col0 = blockIdx.y * 128;

    {
        int r = tid >> 3;
        int q = tid & 7;
        for (int rr = r; rr < 128; rr += 32) {
            int row = row0 + rr;
            float4 v = make_float4(0.f, 0.f, 0.f, 0.f);
            if (row < nrows) v = *(const float4*)(X + (size_t)row * HD + q * 4);
            As[q * 4 + 0][rr] = v.x;
            As[q * 4 + 1][rr] = v.y;
            As[q * 4 + 2][rr] = v.z;
            As[q * 4 + 3][rr] = v.w;
        }
    }
    {
        int r = tid >> 5;
        int q = tid & 31;
        int C = col0 + q * 4;
        int kcol = C >> 5, o = C & 31;
        for (int kk = r; kk < HD; kk += 8) {
            float4 v = *(const float4*)(w2 + kcol * (HD * HD) + kk * HD + o);
            *(float4*)&Bs[kk][q * 4] = v;
        }
    }
    __syncthreads();

    int tr = (tid >> 4) * 8;
    int tc = (tid & 15) * 8;
    float acc[8][8];
#pragma unroll
    for (int a = 0; a < 8; a++)
#pragma unroll
        for (int b = 0; b < 8; b++) acc[a][b] = 0.f;

#pragma unroll
    for (int k = 0; k < HD; k++) {
        float a[8], b[8];
        *(float4*)&a[0] = *(float4*)&As[k][tr];
        *(float4*)&a[4] = *(float4*)&As[k][tr + 4];
        *(float4*)&b[0] = *(float4*)&Bs[k][tc];
        *(float4*)&b[4] = *(float4*)&Bs[k][tc + 4];
#pragma unroll
        for (int i = 0; i < 8; i++)
#pragma unroll
            for (int j = 0; j < 8; j++)
                acc[i][j] += a[i] * b[j];
    }

#pragma unroll
    for (int i = 0; i < 8; i++) {
        int row = row0 + tr + i;
        if (row < nrows) {
            float* dstp = P + (size_t)row * (HD * HD) + col0 + tc;
            *(float4*)(dstp)     = make_float4(acc[i][0], acc[i][1], acc[i][2], acc[i][3]);
            *(float4*)(dstp + 4) = make_float4(acc[i][4], acc[i][5], acc[i][6], acc[i][7]);
        }
    }
}

// ---------------- per-edge message + scatter-add (R4-proven) ----------------------
__global__ void k_edge_msg(int nE, const int* __restrict__ src, const int* __restrict__ dst,
                           const float* __restrict__ h, const float* __restrict__ P,
                           const float* __restrict__ Q, float* __restrict__ agg) {
    int e = (blockIdx.x * blockDim.x + threadIdx.x) >> 5;
    int lane = threadIdx.x & 31;
    if (e >= nE) return;
    int s = src[e];
    int d = dst[e];
    float hv = h[(size_t)e * HD + lane];
    const float4* Pr = (const float4*)(P + (size_t)s * (HD * HD));
    int kq = lane >> 3;
    int og = lane & 7;

    float a0 = 0.f, a1 = 0.f, a2 = 0.f, a3 = 0.f;
#pragma unroll
    for (int it = 0; it < 8; it++) {
        int k = it * 4 + kq;
        float hk = __shfl_sync(0xffffffffu, hv, k);
        float4 v = Pr[k * 8 + og];
        a0 += hk * v.x; a1 += hk * v.y; a2 += hk * v.z; a3 += hk * v.w;
    }
#pragma unroll
    for (int m = 8; m <= 16; m <<= 1) {
        a0 += __shfl_xor_sync(0xffffffffu, a0, m);
        a1 += __shfl_xor_sync(0xffffffffu, a1, m);
        a2 += __shfl_xor_sync(0xffffffffu, a2, m);
        a3 += __shfl_xor_sync(0xffffffffu, a3, m);
    }
    if (lane < 8) {
        float4 q = *(const float4*)(Q + (size_t)s * HD + lane * 4);
        float* ag = agg + (size_t)d * HD + lane * 4;
        atomicAdd(ag + 0, a0 + q.x);
        atomicAdd(ag + 1, a1 + q.y);
        atomicAdd(ag + 2, a2 + q.z);
        atomicAdd(ag + 3, a3 + q.w);
    }
}

// ---------------- finalize + project; re-zeros agg after consuming ---------------
__global__ void k_finalize_proj(const float* __restrict__ Xin, float* __restrict__ Xout,
                                float* __restrict__ agg, const int* __restrict__ deg,
                                const float* __restrict__ rw, const float* __restrict__ rb,
                                const float* __restrict__ pw, const float* __restrict__ pb,
                                float* __restrict__ m, int nrows,
                                float* __restrict__ copy_out) {
    __shared__ float Rs[HD][HD], Pw[HD][HD];
    for (int i = threadIdx.x; i < HD * HD; i += blockDim.x) {
        Rs[i >> 5][i & 31] = rw[i];
        Pw[i >> 5][i & 31] = pw[i];
    }
    __syncthreads();

    int r = (blockIdx.x * blockDim.x + threadIdx.x) >> 5;
    int lane = threadIdx.x & 31;
    if (r >= nrows) return;
    float xv = Xin[(size_t)r * HD + lane];
    float av = agg[(size_t)r * HD + lane];
    agg[(size_t)r * HD + lane] = 0.f;            // restore zero invariant
    float acc = rb[lane] + av / fmaxf((float)deg[r], 1.f);
#pragma unroll
    for (int i = 0; i < HD; i++)
        acc += __shfl_sync(0xffffffffu, xv, i) * Rs[i][lane];
    float xn = fmaxf(acc, 0.f);
    Xout[(size_t)r * HD + lane] = xn;
    if (copy_out) copy_out[(size_t)r * HD + lane] = xn;
    float macc = pb[lane];
#pragma unroll
    for (int i = 0; i < HD; i++)
        macc += __shfl_sync(0xffffffffu, xn, i) * Pw[i][lane];
    m[(size_t)r * HD + lane] = macc;
}

// ---------------- scatter + mean residual (addmean re-zeros agg) ------------------
__global__ void k_scatter(int nA, const int* __restrict__ from, const int* __restrict__ to,
                          const float* __restrict__ m, float* __restrict__ agg) {
    int a = (blockIdx.x * blockDim.x + threadIdx.x) >> 5;
    int lane = threadIdx.x & 31;
    if (a >= nA) return;
    float v = m[(size_t)from[a] * HD + lane];
    atomicAdd(&agg[(size_t)to[a] * HD + lane], v);
}

__global__ void k_addmean(const float* __restrict__ in, float* __restrict__ out,
                          float* __restrict__ agg, const int* __restrict__ deg,
                          int nrows) {
    int i = blockIdx.x * blockDim.x + threadIdx.x;
    if (i >= nrows * HD) return;
    float av = agg[i];
    agg[i] = 0.f;                                // restore zero invariant
    out[i] = in[i] + av / fmaxf((float)deg[i >> 5], 1.f);
}

// ===================================================================================
static inline int cdiv(int a, int b) { return (a + b - 1) / b; }

extern "C" void kernel_launch(void* const* d_in, const int* in_sizes, int n_in,
                              void* d_out, int out_size) {
    const float* node_features   = (const float*)d_in[0];
    const int*   edge_index      = (const int*)d_in[1];
    const float* edge_features   = (const float*)d_in[2];
    const float* clique_features = (const float*)d_in[3];
    const int*   n2c_index       = (const int*)d_in[4];
    const int*   cedge_index     = (const int*)d_in[5];
    const float* cedge_features  = (const float*)d_in[6];
    const float* nn1_w  = (const float*)d_in[7];
    const float* nn1_b  = (const float*)d_in[8];
    const float* nn2_w  = (const float*)d_in[9];
    const float* nn2_b  = (const float*)d_in[10];
    const float* root_w = (const float*)d_in[11];
    const float* root_b = (const float*)d_in[12];
    const float* n2c_w  = (const float*)d_in[13];
    const float* n2c_b  = (const float*)d_in[14];
    const float* cnn1_w = (const float*)d_in[15];
    const float* cnn1_b = (const float*)d_in[16];
    const float* cnn2_w = (const float*)d_in[17];
    const float* cnn2_b = (const float*)d_in[18];
    const float* croot_w = (const float*)d_in[19];
    const float* croot_b = (const float*)d_in[20];
    const float* c2n_w  = (const float*)d_in[21];
    const float* c2n_b  = (const float*)d_in[22];
    float* out = (float*)d_out;

    const int* src  = edge_index;
    const int* dst  = edge_index + NE;
    const int* nid  = n2c_index;
    const int* cid  = n2c_index + NA;
    const int* csrc = cedge_index;
    const int* cdst = cedge_index + NEC;

    float *x, *c, *h, *P, *Q, *aggn, *aggc, *m;
    int* deg;
    cudaGetSymbolAddress((void**)&x, g_x);
    cudaGetSymbolAddress((void**)&c, g_c);
    cudaGetSymbolAddress((void**)&h, g_h);
    cudaGetSymbolAddress((void**)&P, g_P);
    cudaGetSymbolAddress((void**)&Q, g_Q);
    cudaGetSymbolAddress((void**)&aggn, g_aggn);
    cudaGetSymbolAddress((void**)&aggc, g_aggc);
    cudaGetSymbolAddress((void**)&m, g_m);
    cudaGetSymbolAddress((void**)&deg, g_deg);
    const int* deg_dst  = deg;
    const int* deg_cdst = deg + NN;
    const int* deg_cid  = deg + NN + NCL;
    const int* deg_nid  = deg + NN + 2 * NCL;

    const int TB = 256;
    const int DEG_N = 2 * NN + 2 * NCL;
    dim3 gemmGridN(cdiv(NN, 128), 9);   // y==8 is the Q slice
    dim3 gemmGridC(cdiv(NCL, 128), 9);

    // ---- setup: launches #1-3 ----
    k_zero_deg<<<cdiv(DEG_N, TB), TB>>>(deg, DEG_N);
    k_count_all<<<cdiv(NE + NEC + NA, TB), TB>>>(dst, cdst, nid, cid, deg);
    k_edge_mlp_all<<<cdiv((2 * NE + 2 * NEC) * 32, TB), TB>>>(
        edge_features, cedge_features, nn1_w, nn1_b, cnn1_w, cnn1_b, h);

    for (int l = 0; l < 2; l++) {
        const float* xin = (l == 0) ? node_features : x;
        const float* cin = (l == 0) ? clique_features : c;
        int po = l * HD * HD, bo = l * HD;
        const float* h_n = h + (size_t)l * NE * HD;
        const float* h_c = h + (size_t)(2 * NE + l * NEC) * HD;

        // ---- node NNConv ----  (launch #4 on l=0: gemmPQ, profiled)
        k_gemmPQ<<<gemmGridN, 256>>>(xin, NN, nn2_w + l * HD * HD * HD, nn2_b + po, P, Q);
        k_edge_msg<<<cdiv(NE * 32, TB), TB>>>(NE, src, dst, h_n, P, Q, aggn);
        k_finalize_proj<<<cdiv(NN * 32, TB), TB>>>(xin, x, aggn, deg_dst,
                                                   root_w + po, root_b + bo,
                                                   n2c_w + po, n2c_b + bo,
                                                   m, NN, nullptr);
        // ---- Node2Clique ----
        k_scatter<<<cdiv(NA * 32, TB), TB>>>(NA, nid, cid, m, aggc);
        k_addmean<<<cdiv(NCL * HD, TB), TB>>>(cin, c, aggc, deg_cid, NCL);

        // ---- clique NNConv ----
        k_gemmPQ<<<gemmGridC, 256>>>(c, NCL, cnn2_w + l * HD * HD * HD, cnn2_b + po, P, Q);
        k_edge_msg<<<cdiv(NEC * 32, TB), TB>>>(NEC, csrc, cdst, h_c, P, Q, aggc);
        k_finalize_proj<<<cdiv(NCL * 32, TB), TB>>>(c, c, aggc, deg_cdst,
                                                    croot_w + po, croot_b + bo,
                                                    c2n_w + po, c2n_b + bo,
                                                    m, NCL,
                                                    (l == 1) ? (out + (size_t)NN * HD) : nullptr);
        // ---- Clique2Node ----
        k_scatter<<<cdiv(NA * 32, TB), TB>>>(NA, cid, nid, m, aggn);
        k_addmean<<<cdiv(NN * HD, TB), TB>>>(x, (l == 1) ? out : x, aggn, deg_nid, NN);
    }
}